// round 15
// baseline (speedup 1.0000x reference)
#include <cuda_runtime.h>
#include <cuda_bf16.h>
#include <cuda_fp16.h>
#include <math.h>
#include <stdint.h>

// ---------------------------------------------------------------------------
// WindowAttention (Swin-V2) on GB300 — fp16 2-term GEMMs (R13-proven BK=16,
// 3-stage), bf16 3-pass MMA attention at 8 warps.
// ---------------------------------------------------------------------------

#define BW   512
#define NTOK 144
#define DIM  512
#define NH   16
#define HD   32
#define NWIN 64
#define KDIM 512
#define XN   ((size_t)BW * NTOK * DIM)       // 37748736

// device scratch — referenced ONLY from device code (host shadow-ptr trap)
__device__ float g_q[(size_t)BW * NH * NTOK * HD];
__device__ float g_k[(size_t)BW * NH * NTOK * HD];
__device__ float g_v[(size_t)BW * NH * NTOK * HD];
__device__ float g_cpb[NH * 529];

// fp16 operands: A-side single precision, W-side hi/lo split
__device__ __half g_xh[XN];                       // x (fp16)
__device__ __half g_oh[XN];                       // attention output (fp16)
__device__ __half g_wqh[3 * DIM * KDIM], g_wql[3 * DIM * KDIM];
__device__ __half g_wph[DIM * KDIM],     g_wpl[DIM * KDIM];

static __device__ __forceinline__ uint32_t smem_u32(const void* p) {
    uint32_t a;
    asm("{ .reg .u64 t; cvta.to.shared.u64 t, %1; cvt.u32.u64 %0, t; }"
        : "=r"(a) : "l"(p));
    return a;
}

#define LDM4(r, addr) \
    asm volatile("ldmatrix.sync.aligned.m8n8.x4.shared.b16 {%0,%1,%2,%3}, [%4];" \
                 : "=r"((r)[0]), "=r"((r)[1]), "=r"((r)[2]), "=r"((r)[3]) \
                 : "r"(addr))

#define MMA16816(d, a, b0, b1) \
    asm volatile("mma.sync.aligned.m16n8k16.row.col.f32.bf16.bf16.f32 " \
                 "{%0,%1,%2,%3}, {%4,%5,%6,%7}, {%8,%9}, {%0,%1,%2,%3};" \
                 : "+f"((d)[0]), "+f"((d)[1]), "+f"((d)[2]), "+f"((d)[3]) \
                 : "r"((a)[0]), "r"((a)[1]), "r"((a)[2]), "r"((a)[3]), \
                   "r"(b0), "r"(b1))

#define MMAF16(d, a, b0, b1) \
    asm volatile("mma.sync.aligned.m16n8k16.row.col.f32.f16.f16.f32 " \
                 "{%0,%1,%2,%3}, {%4,%5,%6,%7}, {%8,%9}, {%0,%1,%2,%3};" \
                 : "+f"((d)[0]), "+f"((d)[1]), "+f"((d)[2]), "+f"((d)[3]) \
                 : "r"((a)[0]), "r"((a)[1]), "r"((a)[2]), "r"((a)[3]), \
                   "r"(b0), "r"(b1))

#define CP_ASYNC16(saddr, gptr) \
    asm volatile("cp.async.cg.shared.global [%0], [%1], 16;" \
                 :: "r"(saddr), "l"(gptr))
#define CP_COMMIT() asm volatile("cp.async.commit_group;" ::: "memory")
#define CP_WAIT1()  asm volatile("cp.async.wait_group 1;" ::: "memory")

__device__ __forceinline__ void split1(float v, __nv_bfloat16& h, __nv_bfloat16& l) {
    h = __float2bfloat16(v);
    l = __float2bfloat16(v - __bfloat162float(h));
}
__device__ __forceinline__ uint32_t pkbf(__nv_bfloat16 a, __nv_bfloat16 b) {
    return (uint32_t)__bfloat16_as_ushort(a) |
           ((uint32_t)__bfloat16_as_ushort(b) << 16);
}

// ---------------------------------------------------------------------------
// splitters. x -> fp16 single; weights -> fp16 hi + residual lo.
// ---------------------------------------------------------------------------
__global__ void split_x_kernel(const float* __restrict__ src, int n4)
{
    for (int i = blockIdx.x * blockDim.x + threadIdx.x; i < n4;
         i += gridDim.x * blockDim.x) {
        float4 v = ((const float4*)src)[i];
        ((ushort4*)g_xh)[i] = make_ushort4(
            __half_as_ushort(__float2half_rn(v.x)),
            __half_as_ushort(__float2half_rn(v.y)),
            __half_as_ushort(__float2half_rn(v.z)),
            __half_as_ushort(__float2half_rn(v.w)));
    }
}

template <int SEL>   // 1 = w_qkv, 2 = w_proj
__global__ void split_w_kernel(const float* __restrict__ src, int n4)
{
    __half* dh = (SEL == 1) ? g_wqh : g_wph;
    __half* dl = (SEL == 1) ? g_wql : g_wpl;
    for (int i = blockIdx.x * blockDim.x + threadIdx.x; i < n4;
         i += gridDim.x * blockDim.x) {
        float4 v = ((const float4*)src)[i];
        __half h0 = __float2half_rn(v.x);
        __half h1 = __float2half_rn(v.y);
        __half h2 = __float2half_rn(v.z);
        __half h3 = __float2half_rn(v.w);
        ((ushort4*)dh)[i] = make_ushort4(
            __half_as_ushort(h0), __half_as_ushort(h1),
            __half_as_ushort(h2), __half_as_ushort(h3));
        ((ushort4*)dl)[i] = make_ushort4(
            __half_as_ushort(__float2half_rn(v.x - __half2float(h0))),
            __half_as_ushort(__float2half_rn(v.y - __half2float(h1))),
            __half_as_ushort(__float2half_rn(v.z - __half2float(h2))),
            __half_as_ushort(__float2half_rn(v.w - __half2float(h3))));
    }
}

// ---------------------------------------------------------------------------
// CPB MLP — one block per table entry, 128 threads split K
// ---------------------------------------------------------------------------
__global__ __launch_bounds__(128)
void cpb_kernel(const float* __restrict__ w1,
                const float* __restrict__ b1,
                const float* __restrict__ w2)
{
    __shared__ float part[4][NH];
    int idx = blockIdx.x;
    int tid = threadIdx.x;
    int lane = tid & 31;
    int w = tid >> 5;

    int a = idx / 23, bb = idx % 23;
    float ta = (float)(a - 11) * (8.0f / 11.0f);
    float tb = (float)(bb - 11) * (8.0f / 11.0f);
    float t0 = copysignf(log2f(fabsf(ta) + 1.0f) * (1.0f / 3.0f), ta);
    float t1 = copysignf(log2f(fabsf(tb) + 1.0f) * (1.0f / 3.0f), tb);

    float acc[NH];
#pragma unroll
    for (int h = 0; h < NH; h++) acc[h] = 0.0f;
#pragma unroll
    for (int kk = 0; kk < 4; kk++) {
        int k = tid + kk * 128;
        float hid = fmaf(t0, w1[2 * k], fmaf(t1, w1[2 * k + 1], b1[k]));
        hid = fmaxf(hid, 0.0f);
#pragma unroll
        for (int h = 0; h < NH; h++) acc[h] = fmaf(hid, w2[h * 512 + k], acc[h]);
    }
#pragma unroll
    for (int off = 16; off; off >>= 1)
#pragma unroll
        for (int h = 0; h < NH; h++)
            acc[h] += __shfl_xor_sync(0xffffffffu, acc[h], off);
    if (lane == 0)
#pragma unroll
        for (int h = 0; h < NH; h++) part[w][h] = acc[h];
    __syncthreads();
    if (tid < NH) {
        float s = part[0][tid] + part[1][tid] + part[2][tid] + part[3][tid];
        g_cpb[tid * 529 + idx] = 16.0f / (1.0f + __expf(-s));
    }
}

// ---------------------------------------------------------------------------
// fp16 2-term cp.async GEMM (R13-proven): C = Ah*Wh + Ah*Wl.
// CTA 128x128, BK=16, 32 chunks, 3 static stages x 12KB (Ah|Wh|Wl).
// MODE 0: A=g_xh, W=g_wqh/l -> scatter g_q/g_k/g_v (+bias)
// MODE 1: A=g_oh, W=g_wph/l -> C[m][512] + biasA
// ---------------------------------------------------------------------------
#define CHUNKS 32
#define STG 12288
#define NSTAGE 3

template <int MODE>
__global__ __launch_bounds__(256)
void gemm_b(const float* __restrict__ biasA, const float* __restrict__ biasB,
            float* __restrict__ C)
{
    const __half* __restrict__ A  = (MODE == 0) ? g_xh : g_oh;
    const __half* __restrict__ Wh = (MODE == 0) ? g_wqh : g_wph;
    const __half* __restrict__ Wl = (MODE == 0) ? g_wql : g_wpl;

    __shared__ __align__(16) unsigned char sb[NSTAGE][STG];

    const int tid = threadIdx.x;
    const int lane = tid & 31;
    const int w = tid >> 5;
    const int wm = w & 1;
    const int wn = w >> 1;
    const int m0 = blockIdx.y * 128;
    const int n0 = blockIdx.x * 128;

    float acc[4][4][4];
#pragma unroll
    for (int i = 0; i < 4; i++)
#pragma unroll
        for (int j = 0; j < 4; j++)
#pragma unroll
            for (int r = 0; r < 4; r++) acc[i][j][r] = 0.0f;

    const int row = tid >> 1;
    const int kseg = tid & 1;
    const int aoff = (row >> 4) * 512 + (kseg * 2 + ((row >> 3) & 1)) * 128
                   + (row & 7) * 16;
    const int boff = (row >> 4) * 512 + (((row >> 3) & 1) * 2 + kseg) * 128
                   + (row & 7) * 16;
    const size_t ga = (size_t)(m0 + row) * KDIM + kseg * 8;
    const size_t gb = (size_t)(n0 + row) * KDIM + kseg * 8;

    auto issue_stage = [&](int c, int st) {
        uint32_t s = smem_u32(sb[st]);
        CP_ASYNC16(s + aoff,         (const char*)&A[ga + c * 16]);
        CP_ASYNC16(s + 4096 + boff,  (const char*)&Wh[gb + c * 16]);
        CP_ASYNC16(s + 8192 + boff,  (const char*)&Wl[gb + c * 16]);
        CP_COMMIT();
    };

    const uint32_t lmoff = (uint32_t)((lane >> 3) * 128 + (lane & 7) * 16);

    auto compute_stage = [&](int st) {
        uint32_t sbase = smem_u32(sb[st]);
        uint32_t a_lm = sbase + (uint32_t)(wm * 4) * 512u + lmoff;
        uint32_t bh_lm = sbase + 4096u + (uint32_t)(wn * 2) * 512u + lmoff;
        uint32_t bl_lm = bh_lm + 4096u;

        uint32_t ah[4][4], bh[2][4], bl[2][4];
#pragma unroll
        for (int ti = 0; ti < 4; ti++) LDM4(ah[ti], a_lm + ti * 512);
#pragma unroll
        for (int g = 0; g < 2; g++) LDM4(bh[g], bh_lm + g * 512);
#pragma unroll
        for (int ti = 0; ti < 4; ti++)
#pragma unroll
            for (int tj = 0; tj < 4; tj++)
                MMAF16(acc[ti][tj], ah[ti],
                       bh[tj >> 1][(tj & 1) * 2], bh[tj >> 1][(tj & 1) * 2 + 1]);
#pragma unroll
        for (int g = 0; g < 2; g++) LDM4(bl[g], bl_lm + g * 512);
#pragma unroll
        for (int ti = 0; ti < 4; ti++)
#pragma unroll
            for (int tj = 0; tj < 4; tj++)
                MMAF16(acc[ti][tj], ah[ti],
                       bl[tj >> 1][(tj & 1) * 2], bl[tj >> 1][(tj & 1) * 2 + 1]);
    };

    issue_stage(0, 0);
    issue_stage(1, 1);

    int st = 0, st2 = 2;
    for (int c = 0; c < CHUNKS; c++) {
        CP_WAIT1();
        __syncthreads();
        if (c + 2 < CHUNKS) issue_stage(c + 2, st2);   // overlap copy w/ compute
        compute_stage(st);
        st = (st + 1 == NSTAGE) ? 0 : st + 1;
        st2 = (st2 + 1 == NSTAGE) ? 0 : st2 + 1;
    }

#pragma unroll
    for (int ti = 0; ti < 4; ti++) {
#pragma unroll
        for (int half = 0; half < 2; half++) {
            int m = m0 + wm * 64 + ti * 16 + (lane >> 2) + half * 8;
            int bwin = 0, nt = 0;
            if (MODE == 0) { bwin = m / NTOK; nt = m - bwin * NTOK; }
#pragma unroll
            for (int tj = 0; tj < 4; tj++) {
                int n = n0 + wn * 32 + tj * 8 + (lane & 3) * 2;
                float v0 = acc[ti][tj][half * 2 + 0];
                float v1 = acc[ti][tj][half * 2 + 1];
                if (MODE == 0) {
                    int which = n >> 9;
                    int cc = n & 511;
                    int hh = cc >> 5;
                    int dd = cc & 31;
                    float b0 = (which == 0) ? biasA[cc]
                             : (which == 2 ? biasB[cc] : 0.0f);
                    float b1 = (which == 0) ? biasA[cc + 1]
                             : (which == 2 ? biasB[cc + 1] : 0.0f);
                    float* dst = (which == 0) ? g_q : (which == 1 ? g_k : g_v);
                    *(float2*)&dst[((((size_t)bwin * NH + hh) * NTOK) + nt) * HD + dd] =
                        make_float2(v0 + b0, v1 + b1);
                } else {
                    *(float2*)&C[(size_t)m * DIM + n] =
                        make_float2(v0 + biasA[n], v1 + biasA[n + 1]);
                }
            }
        }
    }
}

// ---------------------------------------------------------------------------
// MMA attention — now 256 threads (8 warps): prepass halves, max 2 m-tiles
// per warp (was 3). bf16 3-pass internals; output fp16 single into g_oh.
// ---------------------------------------------------------------------------
#define ASM_K  0
#define ASM_KL 9216
#define ASM_V  18432
#define ASM_VL 27648
#define ASM_Q  36864
#define ASM_QL 46080
#define ASM_BS 55296
#define ATT_SMEM (55296 + 2116)

__global__ __launch_bounds__(256)
void attn_kernel(const float* __restrict__ mask,
                 const float* __restrict__ logit_scale)
{
    extern __shared__ char smc[];
    float* bs = (float*)(smc + ASM_BS);

    int bid = blockIdx.x;
    int b = bid >> 4;
    int h = bid & 15;
    int tid = threadIdx.x;
    int w = tid >> 5;
    int lane = tid & 31;

    for (int t = tid; t < 529; t += 256) bs[t] = g_cpb[h * 529 + t];

    size_t base = (size_t)bid * (NTOK * HD);
    float scale = __expf(fminf(logit_scale[h], 4.605170185988092f));

    for (int r = tid; r < NTOK; r += 256) {
        float buf[HD];
#pragma unroll
        for (int p = 0; p < 8; p++)
            *(float4*)&buf[p * 4] = *(const float4*)&g_q[base + (size_t)r * HD + p * 4];
        float ss = 0.0f;
#pragma unroll
        for (int d = 0; d < HD; d++) ss = fmaf(buf[d], buf[d], ss);
        float inv = scale / fmaxf(sqrtf(ss), 1e-12f);
#pragma unroll
        for (int d = 0; d < HD; d++) {
            __nv_bfloat16 hh, ll;
            split1(buf[d] * inv, hh, ll);
            int off = (r >> 4) * 1024 + (d >> 4) * 512
                    + (((d >> 3) & 1) * 2 + ((r >> 3) & 1)) * 128
                    + (r & 7) * 16 + (d & 7) * 2;
            *(__nv_bfloat16*)(smc + ASM_Q + off) = hh;
            *(__nv_bfloat16*)(smc + ASM_QL + off) = ll;
        }
#pragma unroll
        for (int p = 0; p < 8; p++)
            *(float4*)&buf[p * 4] = *(const float4*)&g_k[base + (size_t)r * HD + p * 4];
        ss = 0.0f;
#pragma unroll
        for (int d = 0; d < HD; d++) ss = fmaf(buf[d], buf[d], ss);
        inv = 1.0f / fmaxf(sqrtf(ss), 1e-12f);
#pragma unroll
        for (int d = 0; d < HD; d++) {
            __nv_bfloat16 hh, ll;
            split1(buf[d] * inv, hh, ll);
            int off = (r >> 4) * 1024 + (d >> 4) * 512
                    + (((r >> 3) & 1) * 2 + ((d >> 3) & 1)) * 128
                    + (r & 7) * 16 + (d & 7) * 2;
            *(__nv_bfloat16*)(smc + ASM_K + off) = hh;
            *(__nv_bfloat16*)(smc + ASM_KL + off) = ll;
        }
#pragma unroll
        for (int p = 0; p < 8; p++)
            *(float4*)&buf[p * 4] = *(const float4*)&g_v[base + (size_t)r * HD + p * 4];
#pragma unroll
        for (int d = 0; d < HD; d++) {
            __nv_bfloat16 hh, ll;
            split1(buf[d], hh, ll);
            int off = (d >> 4) * 4608 + (r >> 4) * 512
                    + (((d >> 3) & 1) * 2 + ((r >> 3) & 1)) * 128
                    + (d & 7) * 16 + (r & 7) * 2;
            *(__nv_bfloat16*)(smc + ASM_V + off) = hh;
            *(__nv_bfloat16*)(smc + ASM_VL + off) = ll;
        }
    }
    __syncthreads();

    const float* mbase = mask + (size_t)(b & (NWIN - 1)) * (NTOK * NTOK);
    const uint32_t lmoff = (uint32_t)((lane >> 3) * 128 + (lane & 7) * 16);
    const uint32_t kh_b = smem_u32(smc + ASM_K) + lmoff;
    const uint32_t kl_b = smem_u32(smc + ASM_KL) + lmoff;
    const uint32_t vh_b = smem_u32(smc + ASM_V) + lmoff;
    const uint32_t vl_b = smem_u32(smc + ASM_VL) + lmoff;
    const uint32_t qh_b = smem_u32(smc + ASM_Q) + lmoff;
    const uint32_t ql_b = smem_u32(smc + ASM_QL) + lmoff;

    for (int mt = w; mt < 9; mt += 8) {
        float s[18][4];
#pragma unroll
        for (int tj = 0; tj < 18; tj++)
#pragma unroll
            for (int r = 0; r < 4; r++) s[tj][r] = 0.0f;

        uint32_t aq[2][4], aql[2][4];
#pragma unroll
        for (int u = 0; u < 2; u++) {
            LDM4(aq[u], qh_b + mt * 1024 + u * 512);
            LDM4(aql[u], ql_b + mt * 1024 + u * 512);
        }
#pragma unroll
        for (int t2 = 0; t2 < 9; t2++) {
            uint32_t kbh[2][4], kbl[2][4];
#pragma unroll
            for (int u = 0; u < 2; u++) {
                LDM4(kbh[u], kh_b + t2 * 1024 + u * 512);
                LDM4(kbl[u], kl_b + t2 * 1024 + u * 512);
            }
#pragma unroll
            for (int u = 0; u < 2; u++)
#pragma unroll
                for (int hf = 0; hf < 2; hf++) {
                    int tj = t2 * 2 + hf;
                    MMA16816(s[tj], aq[u], kbh[u][hf * 2], kbh[u][hf * 2 + 1]);
                    MMA16816(s[tj], aq[u], kbl[u][hf * 2], kbl[u][hf * 2 + 1]);
                    MMA16816(s[tj], aql[u], kbh[u][hf * 2], kbh[u][hf * 2 + 1]);
                }
        }

        int r0 = mt * 16 + (lane >> 2);
        int r1 = r0 + 8;
        int yi0 = r0 / 12, xi0 = r0 - yi0 * 12;
        int yi1 = r1 / 12, xi1 = r1 - yi1 * 12;
        float mx0 = -1e30f, mx1 = -1e30f;
#pragma unroll
        for (int tj = 0; tj < 18; tj++) {
            int j0 = tj * 8 + (lane & 3) * 2;
            int j1 = j0 + 1;
            int yj0 = j0 / 12, xj0 = j0 - yj0 * 12;
            int yj1 = j1 / 12, xj1 = j1 - yj1 * 12;
            float2 mk0 = *(const float2*)&mbase[r0 * NTOK + j0];
            float2 mk1 = *(const float2*)&mbase[r1 * NTOK + j0];
            s[tj][0] += bs[(yi0 - yj0 + 11) * 23 + (xi0 - xj0 + 11)] + mk0.x;
            s[tj][1] += bs[(yi0 - yj1 + 11) * 23 + (xi0 - xj1 + 11)] + mk0.y;
            s[tj][2] += bs[(yi1 - yj0 + 11) * 23 + (xi1 - xj0 + 11)] + mk1.x;
            s[tj][3] += bs[(yi1 - yj1 + 11) * 23 + (xi1 - xj1 + 11)] + mk1.y;
            mx0 = fmaxf(mx0, fmaxf(s[tj][0], s[tj][1]));
            mx1 = fmaxf(mx1, fmaxf(s[tj][2], s[tj][3]));
        }
        mx0 = fmaxf(mx0, __shfl_xor_sync(0xffffffffu, mx0, 1));
        mx0 = fmaxf(mx0, __shfl_xor_sync(0xffffffffu, mx0, 2));
        mx1 = fmaxf(mx1, __shfl_xor_sync(0xffffffffu, mx1, 1));
        mx1 = fmaxf(mx1, __shfl_xor_sync(0xffffffffu, mx1, 2));

        float sum0 = 0.0f, sum1 = 0.0f;
#pragma unroll
        for (int tj = 0; tj < 18; tj++) {
            s[tj][0] = __expf(s[tj][0] - mx0);
            s[tj][1] = __expf(s[tj][1] - mx0);
            s[tj][2] = __expf(s[tj][2] - mx1);
            s[tj][3] = __expf(s[tj][3] - mx1);
            sum0 += s[tj][0] + s[tj][1];
            sum1 += s[tj][2] + s[tj][3];
        }
        sum0 += __shfl_xor_sync(0xffffffffu, sum0, 1);
        sum0 += __shfl_xor_sync(0xffffffffu, sum0, 2);
        sum1 += __shfl_xor_sync(0xffffffffu, sum1, 1);
        sum1 += __shfl_xor_sync(0xffffffffu, sum1, 2);
        float inv0 = 1.0f / sum0;
        float inv1 = 1.0f / sum1;

        float o[4][4];
#pragma unroll
        for (int nd = 0; nd < 4; nd++)
#pragma unroll
            for (int r = 0; r < 4; r++) o[nd][r] = 0.0f;

#pragma unroll
        for (int t = 0; t < 9; t++) {
            uint32_t ph[4], pl[4];
#pragma unroll
            for (int rg = 0; rg < 4; rg++) {
                float a = s[t * 2 + (rg >> 1)][(rg & 1) * 2 + 0];
                float c = s[t * 2 + (rg >> 1)][(rg & 1) * 2 + 1];
                __nv_bfloat16 ha, la, hc, lc;
                split1(a, ha, la);
                split1(c, hc, lc);
                ph[rg] = pkbf(ha, hc);
                pl[rg] = pkbf(la, lc);
            }
            uint32_t vbh[2][4], vbl[2][4];
#pragma unroll
            for (int u = 0; u < 2; u++) {
                LDM4(vbh[u], vh_b + u * 4608 + t * 512);
                LDM4(vbl[u], vl_b + u * 4608 + t * 512);
            }
#pragma unroll
            for (int nd = 0; nd < 4; nd++) {
                int u = nd >> 1, rr = (nd & 1) * 2;
                MMA16816(o[nd], ph, vbh[u][rr], vbh[u][rr + 1]);
                MMA16816(o[nd], pl, vbh[u][rr], vbh[u][rr + 1]);
                MMA16816(o[nd], ph, vbl[u][rr], vbl[u][rr + 1]);
            }
        }

        size_t ob = ((size_t)b * NTOK) * DIM + h * HD;
#pragma unroll
        for (int nd = 0; nd < 4; nd++) {
            int d = nd * 8 + (lane & 3) * 2;
            float a0 = o[nd][0] * inv0, a1 = o[nd][1] * inv0;
            float a2 = o[nd][2] * inv1, a3 = o[nd][3] * inv1;
            size_t i0 = ob + (size_t)r0 * DIM + d;
            size_t i1 = ob + (size_t)r1 * DIM + d;
            *(ushort2*)&g_oh[i0] = make_ushort2(
                __half_as_ushort(__float2half_rn(a0)),
                __half_as_ushort(__float2half_rn(a1)));
            *(ushort2*)&g_oh[i1] = make_ushort2(
                __half_as_ushort(__float2half_rn(a2)),
                __half_as_ushort(__float2half_rn(a3)));
        }
    }
}

// ---------------------------------------------------------------------------
// launch — size-based input resolution (order-robust)
// ---------------------------------------------------------------------------
extern "C" void kernel_launch(void* const* d_in, const int* in_sizes, int n_in,
                              void* d_out, int out_size)
{
    int ix = 0, imask = 1, iwqkv = 2, ils = 5, iw1 = 6, iw2 = 8, iwproj = 9;
    int small[4] = {3, 4, 7, 10};
    int ns = 0;
    int sm_tmp[8];
    int fx = -1, fmask = -1, fwqkv = -1, fls = -1, fw1 = -1, fw2 = -1, fwp = -1;
    for (int i = 0; i < n_in; i++) {
        switch (in_sizes[i]) {
            case 37748736: fx = i; break;
            case 1327104:  fmask = i; break;
            case 786432:   fwqkv = i; break;
            case 16:       fls = i; break;
            case 1024:     fw1 = i; break;
            case 8192:     fw2 = i; break;
            case 262144:   fwp = i; break;
            case 512:      if (ns < 8) sm_tmp[ns++] = i; break;
            default: break;
        }
    }
    if (fx >= 0 && fmask >= 0 && fwqkv >= 0 && fls >= 0 && fw1 >= 0 &&
        fw2 >= 0 && fwp >= 0 && ns >= 4) {
        ix = fx; imask = fmask; iwqkv = fwqkv; ils = fls;
        iw1 = fw1; iw2 = fw2; iwproj = fwp;
        for (int t = 0; t < 4; t++) small[t] = sm_tmp[t];
    }

    const float* x           = (const float*)d_in[ix];
    const float* mask        = (const float*)d_in[imask];
    const float* w_qkv       = (const float*)d_in[iwqkv];
    const float* q_bias      = (const float*)d_in[small[0]];
    const float* v_bias      = (const float*)d_in[small[1]];
    const float* logit_scale = (const float*)d_in[ils];
    const float* w1          = (const float*)d_in[iw1];
    const float* b1          = (const float*)d_in[small[2]];
    const float* w2          = (const float*)d_in[iw2];
    const float* w_proj      = (const float*)d_in[iwproj];
    const float* b_proj      = (const float*)d_in[small[3]];
    float* out = (float*)d_out;
    (void)out_size;

    cudaFuncSetAttribute(attn_kernel,
                         cudaFuncAttributeMaxDynamicSharedMemorySize, ATT_SMEM);

    // 0) operand prep: x -> fp16; weights -> fp16 hi/lo
    split_x_kernel<<<4096, 256>>>(x, (int)(XN / 4));
    split_w_kernel<1><<<768, 256>>>(w_qkv, 3 * DIM * KDIM / 4);
    split_w_kernel<2><<<256, 256>>>(w_proj, DIM * KDIM / 4);

    // 1) CPB bias table
    cpb_kernel<<<529, 128>>>(w1, b1, w2);

    // 2) QKV: (73728 x 512) @ (1536 x 512)^T — fp16 2-term, BK=16 (R13)
    {
        dim3 grid(1536 / 128, (BW * NTOK) / 128);
        gemm_b<0><<<grid, 256>>>(q_bias, v_bias, nullptr);
    }

    // 3) attention per (b,h) — bf16 3-pass MMA, 8 warps
    attn_kernel<<<BW * NH, 256, ATT_SMEM>>>(mask, logit_scale);

    // 4) proj: (73728 x 512) @ (512 x 512)^T — fp16 2-term, BK=16 (R13)
    {
        dim3 grid(DIM / 128, (BW * NTOK) / 128);
        gemm_b<1><<<grid, 256>>>(b_proj, nullptr, out);
    }
}

// round 16
// speedup vs baseline: 1.1642x; 1.1642x over previous
#include <cuda_runtime.h>
#include <cuda_bf16.h>
#include <cuda_fp16.h>
#include <math.h>
#include <stdint.h>

// ---------------------------------------------------------------------------
// WindowAttention (Swin-V2) on GB300 — R13-proven fp16 2-term GEMMs (BK=16,
// 3-stage cp.async), 4-warp bf16 3-pass MMA attention, fused splitter.
// ---------------------------------------------------------------------------

#define BW   512
#define NTOK 144
#define DIM  512
#define NH   16
#define HD   32
#define NWIN 64
#define KDIM 512
#define XN   ((size_t)BW * NTOK * DIM)       // 37748736

// device scratch — referenced ONLY from device code (host shadow-ptr trap)
__device__ float g_q[(size_t)BW * NH * NTOK * HD];
__device__ float g_k[(size_t)BW * NH * NTOK * HD];
__device__ float g_v[(size_t)BW * NH * NTOK * HD];
__device__ float g_cpb[NH * 529];

// fp16 operands: A-side single precision, W-side hi/lo split
__device__ __half g_xh[XN];                       // x (fp16)
__device__ __half g_oh[XN];                       // attention output (fp16)
__device__ __half g_wqh[3 * DIM * KDIM], g_wql[3 * DIM * KDIM];
__device__ __half g_wph[DIM * KDIM],     g_wpl[DIM * KDIM];

static __device__ __forceinline__ uint32_t smem_u32(const void* p) {
    uint32_t a;
    asm("{ .reg .u64 t; cvta.to.shared.u64 t, %1; cvt.u32.u64 %0, t; }"
        : "=r"(a) : "l"(p));
    return a;
}

#define LDM4(r, addr) \
    asm volatile("ldmatrix.sync.aligned.m8n8.x4.shared.b16 {%0,%1,%2,%3}, [%4];" \
                 : "=r"((r)[0]), "=r"((r)[1]), "=r"((r)[2]), "=r"((r)[3]) \
                 : "r"(addr))

#define MMA16816(d, a, b0, b1) \
    asm volatile("mma.sync.aligned.m16n8k16.row.col.f32.bf16.bf16.f32 " \
                 "{%0,%1,%2,%3}, {%4,%5,%6,%7}, {%8,%9}, {%0,%1,%2,%3};" \
                 : "+f"((d)[0]), "+f"((d)[1]), "+f"((d)[2]), "+f"((d)[3]) \
                 : "r"((a)[0]), "r"((a)[1]), "r"((a)[2]), "r"((a)[3]), \
                   "r"(b0), "r"(b1))

#define MMAF16(d, a, b0, b1) \
    asm volatile("mma.sync.aligned.m16n8k16.row.col.f32.f16.f16.f32 " \
                 "{%0,%1,%2,%3}, {%4,%5,%6,%7}, {%8,%9}, {%0,%1,%2,%3};" \
                 : "+f"((d)[0]), "+f"((d)[1]), "+f"((d)[2]), "+f"((d)[3]) \
                 : "r"((a)[0]), "r"((a)[1]), "r"((a)[2]), "r"((a)[3]), \
                   "r"(b0), "r"(b1))

#define CP_ASYNC16(saddr, gptr) \
    asm volatile("cp.async.cg.shared.global [%0], [%1], 16;" \
                 :: "r"(saddr), "l"(gptr))
#define CP_COMMIT() asm volatile("cp.async.commit_group;" ::: "memory")
#define CP_WAIT1()  asm volatile("cp.async.wait_group 1;" ::: "memory")

__device__ __forceinline__ void split1(float v, __nv_bfloat16& h, __nv_bfloat16& l) {
    h = __float2bfloat16(v);
    l = __float2bfloat16(v - __bfloat162float(h));
}
__device__ __forceinline__ uint32_t pkbf(__nv_bfloat16 a, __nv_bfloat16 b) {
    return (uint32_t)__bfloat16_as_ushort(a) |
           ((uint32_t)__bfloat16_as_ushort(b) << 16);
}

// ---------------------------------------------------------------------------
// fused splitter: one launch covers x (fp16 single) + w_qkv + w_proj (hi/lo).
// Block regions: [0, XB) -> x, [XB, XB+QB) -> w_qkv, [XB+QB, XB+QB+PB) -> w_proj
// ---------------------------------------------------------------------------
#define SPL_XB 4096
#define SPL_QB 192
#define SPL_PB 64
#define SPL_BLOCKS (SPL_XB + SPL_QB + SPL_PB)

__global__ void split_all_kernel(const float* __restrict__ x,
                                 const float* __restrict__ wq,
                                 const float* __restrict__ wp)
{
    int blk = blockIdx.x;
    if (blk < SPL_XB) {
        int n4 = (int)(XN / 4);
        for (int i = blk * blockDim.x + threadIdx.x; i < n4;
             i += SPL_XB * blockDim.x) {
            float4 v = ((const float4*)x)[i];
            ((ushort4*)g_xh)[i] = make_ushort4(
                __half_as_ushort(__float2half_rn(v.x)),
                __half_as_ushort(__float2half_rn(v.y)),
                __half_as_ushort(__float2half_rn(v.z)),
                __half_as_ushort(__float2half_rn(v.w)));
        }
        return;
    }
    const float* src;
    __half *dh, *dl;
    int n4, b0, nb;
    if (blk < SPL_XB + SPL_QB) {
        src = wq; dh = g_wqh; dl = g_wql;
        n4 = 3 * DIM * KDIM / 4; b0 = SPL_XB; nb = SPL_QB;
    } else {
        src = wp; dh = g_wph; dl = g_wpl;
        n4 = DIM * KDIM / 4; b0 = SPL_XB + SPL_QB; nb = SPL_PB;
    }
    for (int i = (blk - b0) * blockDim.x + threadIdx.x; i < n4;
         i += nb * blockDim.x) {
        float4 v = ((const float4*)src)[i];
        __half h0 = __float2half_rn(v.x);
        __half h1 = __float2half_rn(v.y);
        __half h2 = __float2half_rn(v.z);
        __half h3 = __float2half_rn(v.w);
        ((ushort4*)dh)[i] = make_ushort4(
            __half_as_ushort(h0), __half_as_ushort(h1),
            __half_as_ushort(h2), __half_as_ushort(h3));
        ((ushort4*)dl)[i] = make_ushort4(
            __half_as_ushort(__float2half_rn(v.x - __half2float(h0))),
            __half_as_ushort(__float2half_rn(v.y - __half2float(h1))),
            __half_as_ushort(__float2half_rn(v.z - __half2float(h2))),
            __half_as_ushort(__float2half_rn(v.w - __half2float(h3))));
    }
}

// ---------------------------------------------------------------------------
// CPB MLP — one block per table entry, 128 threads split K
// ---------------------------------------------------------------------------
__global__ __launch_bounds__(128)
void cpb_kernel(const float* __restrict__ w1,
                const float* __restrict__ b1,
                const float* __restrict__ w2)
{
    __shared__ float part[4][NH];
    int idx = blockIdx.x;
    int tid = threadIdx.x;
    int lane = tid & 31;
    int w = tid >> 5;

    int a = idx / 23, bb = idx % 23;
    float ta = (float)(a - 11) * (8.0f / 11.0f);
    float tb = (float)(bb - 11) * (8.0f / 11.0f);
    float t0 = copysignf(log2f(fabsf(ta) + 1.0f) * (1.0f / 3.0f), ta);
    float t1 = copysignf(log2f(fabsf(tb) + 1.0f) * (1.0f / 3.0f), tb);

    float acc[NH];
#pragma unroll
    for (int h = 0; h < NH; h++) acc[h] = 0.0f;
#pragma unroll
    for (int kk = 0; kk < 4; kk++) {
        int k = tid + kk * 128;
        float hid = fmaf(t0, w1[2 * k], fmaf(t1, w1[2 * k + 1], b1[k]));
        hid = fmaxf(hid, 0.0f);
#pragma unroll
        for (int h = 0; h < NH; h++) acc[h] = fmaf(hid, w2[h * 512 + k], acc[h]);
    }
#pragma unroll
    for (int off = 16; off; off >>= 1)
#pragma unroll
        for (int h = 0; h < NH; h++)
            acc[h] += __shfl_xor_sync(0xffffffffu, acc[h], off);
    if (lane == 0)
#pragma unroll
        for (int h = 0; h < NH; h++) part[w][h] = acc[h];
    __syncthreads();
    if (tid < NH) {
        float s = part[0][tid] + part[1][tid] + part[2][tid] + part[3][tid];
        g_cpb[tid * 529 + idx] = 16.0f / (1.0f + __expf(-s));
    }
}

// ---------------------------------------------------------------------------
// fp16 2-term cp.async GEMM (R13-proven): C = Ah*Wh + Ah*Wl.
// CTA 128x128, BK=16, 32 chunks, 3 static stages x 12KB (Ah|Wh|Wl).
// MODE 0: A=g_xh, W=g_wqh/l -> scatter g_q/g_k/g_v (+bias)
// MODE 1: A=g_oh, W=g_wph/l -> C[m][512] + biasA
// ---------------------------------------------------------------------------
#define CHUNKS 32
#define STG 12288
#define NSTAGE 3

template <int MODE>
__global__ __launch_bounds__(256)
void gemm_b(const float* __restrict__ biasA, const float* __restrict__ biasB,
            float* __restrict__ C)
{
    const __half* __restrict__ A  = (MODE == 0) ? g_xh : g_oh;
    const __half* __restrict__ Wh = (MODE == 0) ? g_wqh : g_wph;
    const __half* __restrict__ Wl = (MODE == 0) ? g_wql : g_wpl;

    __shared__ __align__(16) unsigned char sb[NSTAGE][STG];

    const int tid = threadIdx.x;
    const int lane = tid & 31;
    const int w = tid >> 5;
    const int wm = w & 1;
    const int wn = w >> 1;
    const int m0 = blockIdx.y * 128;
    const int n0 = blockIdx.x * 128;

    float acc[4][4][4];
#pragma unroll
    for (int i = 0; i < 4; i++)
#pragma unroll
        for (int j = 0; j < 4; j++)
#pragma unroll
            for (int r = 0; r < 4; r++) acc[i][j][r] = 0.0f;

    const int row = tid >> 1;
    const int kseg = tid & 1;
    const int aoff = (row >> 4) * 512 + (kseg * 2 + ((row >> 3) & 1)) * 128
                   + (row & 7) * 16;
    const int boff = (row >> 4) * 512 + (((row >> 3) & 1) * 2 + kseg) * 128
                   + (row & 7) * 16;
    const size_t ga = (size_t)(m0 + row) * KDIM + kseg * 8;
    const size_t gb = (size_t)(n0 + row) * KDIM + kseg * 8;

    auto issue_stage = [&](int c, int st) {
        uint32_t s = smem_u32(sb[st]);
        CP_ASYNC16(s + aoff,         (const char*)&A[ga + c * 16]);
        CP_ASYNC16(s + 4096 + boff,  (const char*)&Wh[gb + c * 16]);
        CP_ASYNC16(s + 8192 + boff,  (const char*)&Wl[gb + c * 16]);
        CP_COMMIT();
    };

    const uint32_t lmoff = (uint32_t)((lane >> 3) * 128 + (lane & 7) * 16);

    auto compute_stage = [&](int st) {
        uint32_t sbase = smem_u32(sb[st]);
        uint32_t a_lm = sbase + (uint32_t)(wm * 4) * 512u + lmoff;
        uint32_t bh_lm = sbase + 4096u + (uint32_t)(wn * 2) * 512u + lmoff;
        uint32_t bl_lm = bh_lm + 4096u;

        uint32_t ah[4][4], bh[2][4], bl[2][4];
#pragma unroll
        for (int ti = 0; ti < 4; ti++) LDM4(ah[ti], a_lm + ti * 512);
#pragma unroll
        for (int g = 0; g < 2; g++) LDM4(bh[g], bh_lm + g * 512);
#pragma unroll
        for (int ti = 0; ti < 4; ti++)
#pragma unroll
            for (int tj = 0; tj < 4; tj++)
                MMAF16(acc[ti][tj], ah[ti],
                       bh[tj >> 1][(tj & 1) * 2], bh[tj >> 1][(tj & 1) * 2 + 1]);
#pragma unroll
        for (int g = 0; g < 2; g++) LDM4(bl[g], bl_lm + g * 512);
#pragma unroll
        for (int ti = 0; ti < 4; ti++)
#pragma unroll
            for (int tj = 0; tj < 4; tj++)
                MMAF16(acc[ti][tj], ah[ti],
                       bl[tj >> 1][(tj & 1) * 2], bl[tj >> 1][(tj & 1) * 2 + 1]);
    };

    issue_stage(0, 0);
    issue_stage(1, 1);

    int st = 0, st2 = 2;
    for (int c = 0; c < CHUNKS; c++) {
        CP_WAIT1();
        __syncthreads();
        if (c + 2 < CHUNKS) issue_stage(c + 2, st2);   // overlap copy w/ compute
        compute_stage(st);
        st = (st + 1 == NSTAGE) ? 0 : st + 1;
        st2 = (st2 + 1 == NSTAGE) ? 0 : st2 + 1;
    }

#pragma unroll
    for (int ti = 0; ti < 4; ti++) {
#pragma unroll
        for (int half = 0; half < 2; half++) {
            int m = m0 + wm * 64 + ti * 16 + (lane >> 2) + half * 8;
            int bwin = 0, nt = 0;
            if (MODE == 0) { bwin = m / NTOK; nt = m - bwin * NTOK; }
#pragma unroll
            for (int tj = 0; tj < 4; tj++) {
                int n = n0 + wn * 32 + tj * 8 + (lane & 3) * 2;
                float v0 = acc[ti][tj][half * 2 + 0];
                float v1 = acc[ti][tj][half * 2 + 1];
                if (MODE == 0) {
                    int which = n >> 9;
                    int cc = n & 511;
                    int hh = cc >> 5;
                    int dd = cc & 31;
                    float b0 = (which == 0) ? biasA[cc]
                             : (which == 2 ? biasB[cc] : 0.0f);
                    float b1 = (which == 0) ? biasA[cc + 1]
                             : (which == 2 ? biasB[cc + 1] : 0.0f);
                    float* dst = (which == 0) ? g_q : (which == 1 ? g_k : g_v);
                    *(float2*)&dst[((((size_t)bwin * NH + hh) * NTOK) + nt) * HD + dd] =
                        make_float2(v0 + b0, v1 + b1);
                } else {
                    *(float2*)&C[(size_t)m * DIM + n] =
                        make_float2(v0 + biasA[n], v1 + biasA[n + 1]);
                }
            }
        }
    }
}

// ---------------------------------------------------------------------------
// MMA attention (R13-proven, 128 threads / 4 warps, 9 m-tiles of 16).
// bf16 3-pass internals; output fp16 single into g_oh.
// ---------------------------------------------------------------------------
#define ASM_K  0
#define ASM_KL 9216
#define ASM_V  18432
#define ASM_VL 27648
#define ASM_Q  36864
#define ASM_QL 46080
#define ASM_BS 55296
#define ATT_SMEM (55296 + 2116)

__global__ __launch_bounds__(128)
void attn_kernel(const float* __restrict__ mask,
                 const float* __restrict__ logit_scale)
{
    extern __shared__ char smc[];
    float* bs = (float*)(smc + ASM_BS);

    int bid = blockIdx.x;
    int b = bid >> 4;
    int h = bid & 15;
    int tid = threadIdx.x;
    int w = tid >> 5;
    int lane = tid & 31;

    for (int t = tid; t < 529; t += 128) bs[t] = g_cpb[h * 529 + t];

    size_t base = (size_t)bid * (NTOK * HD);
    float scale = __expf(fminf(logit_scale[h], 4.605170185988092f));

    for (int r = tid; r < NTOK; r += 128) {
        float buf[HD];
#pragma unroll
        for (int p = 0; p < 8; p++)
            *(float4*)&buf[p * 4] = *(const float4*)&g_q[base + (size_t)r * HD + p * 4];
        float ss = 0.0f;
#pragma unroll
        for (int d = 0; d < HD; d++) ss = fmaf(buf[d], buf[d], ss);
        float inv = scale / fmaxf(sqrtf(ss), 1e-12f);
#pragma unroll
        for (int d = 0; d < HD; d++) {
            __nv_bfloat16 hh, ll;
            split1(buf[d] * inv, hh, ll);
            int off = (r >> 4) * 1024 + (d >> 4) * 512
                    + (((d >> 3) & 1) * 2 + ((r >> 3) & 1)) * 128
                    + (r & 7) * 16 + (d & 7) * 2;
            *(__nv_bfloat16*)(smc + ASM_Q + off) = hh;
            *(__nv_bfloat16*)(smc + ASM_QL + off) = ll;
        }
#pragma unroll
        for (int p = 0; p < 8; p++)
            *(float4*)&buf[p * 4] = *(const float4*)&g_k[base + (size_t)r * HD + p * 4];
        ss = 0.0f;
#pragma unroll
        for (int d = 0; d < HD; d++) ss = fmaf(buf[d], buf[d], ss);
        inv = 1.0f / fmaxf(sqrtf(ss), 1e-12f);
#pragma unroll
        for (int d = 0; d < HD; d++) {
            __nv_bfloat16 hh, ll;
            split1(buf[d] * inv, hh, ll);
            int off = (r >> 4) * 1024 + (d >> 4) * 512
                    + (((r >> 3) & 1) * 2 + ((d >> 3) & 1)) * 128
                    + (r & 7) * 16 + (d & 7) * 2;
            *(__nv_bfloat16*)(smc + ASM_K + off) = hh;
            *(__nv_bfloat16*)(smc + ASM_KL + off) = ll;
        }
#pragma unroll
        for (int p = 0; p < 8; p++)
            *(float4*)&buf[p * 4] = *(const float4*)&g_v[base + (size_t)r * HD + p * 4];
#pragma unroll
        for (int d = 0; d < HD; d++) {
            __nv_bfloat16 hh, ll;
            split1(buf[d], hh, ll);
            int off = (d >> 4) * 4608 + (r >> 4) * 512
                    + (((d >> 3) & 1) * 2 + ((r >> 3) & 1)) * 128
                    + (d & 7) * 16 + (r & 7) * 2;
            *(__nv_bfloat16*)(smc + ASM_V + off) = hh;
            *(__nv_bfloat16*)(smc + ASM_VL + off) = ll;
        }
    }
    __syncthreads();

    const float* mbase = mask + (size_t)(b & (NWIN - 1)) * (NTOK * NTOK);
    const uint32_t lmoff = (uint32_t)((lane >> 3) * 128 + (lane & 7) * 16);
    const uint32_t kh_b = smem_u32(smc + ASM_K) + lmoff;
    const uint32_t kl_b = smem_u32(smc + ASM_KL) + lmoff;
    const uint32_t vh_b = smem_u32(smc + ASM_V) + lmoff;
    const uint32_t vl_b = smem_u32(smc + ASM_VL) + lmoff;
    const uint32_t qh_b = smem_u32(smc + ASM_Q) + lmoff;
    const uint32_t ql_b = smem_u32(smc + ASM_QL) + lmoff;

    for (int mt = w; mt < 9; mt += 4) {
        float s[18][4];
#pragma unroll
        for (int tj = 0; tj < 18; tj++)
#pragma unroll
            for (int r = 0; r < 4; r++) s[tj][r] = 0.0f;

        uint32_t aq[2][4], aql[2][4];
#pragma unroll
        for (int u = 0; u < 2; u++) {
            LDM4(aq[u], qh_b + mt * 1024 + u * 512);
            LDM4(aql[u], ql_b + mt * 1024 + u * 512);
        }
#pragma unroll
        for (int t2 = 0; t2 < 9; t2++) {
            uint32_t kbh[2][4], kbl[2][4];
#pragma unroll
            for (int u = 0; u < 2; u++) {
                LDM4(kbh[u], kh_b + t2 * 1024 + u * 512);
                LDM4(kbl[u], kl_b + t2 * 1024 + u * 512);
            }
#pragma unroll
            for (int u = 0; u < 2; u++)
#pragma unroll
                for (int hf = 0; hf < 2; hf++) {
                    int tj = t2 * 2 + hf;
                    MMA16816(s[tj], aq[u], kbh[u][hf * 2], kbh[u][hf * 2 + 1]);
                    MMA16816(s[tj], aq[u], kbl[u][hf * 2], kbl[u][hf * 2 + 1]);
                    MMA16816(s[tj], aql[u], kbh[u][hf * 2], kbh[u][hf * 2 + 1]);
                }
        }

        int r0 = mt * 16 + (lane >> 2);
        int r1 = r0 + 8;
        int yi0 = r0 / 12, xi0 = r0 - yi0 * 12;
        int yi1 = r1 / 12, xi1 = r1 - yi1 * 12;
        float mx0 = -1e30f, mx1 = -1e30f;
#pragma unroll
        for (int tj = 0; tj < 18; tj++) {
            int j0 = tj * 8 + (lane & 3) * 2;
            int j1 = j0 + 1;
            int yj0 = j0 / 12, xj0 = j0 - yj0 * 12;
            int yj1 = j1 / 12, xj1 = j1 - yj1 * 12;
            float2 mk0 = *(const float2*)&mbase[r0 * NTOK + j0];
            float2 mk1 = *(const float2*)&mbase[r1 * NTOK + j0];
            s[tj][0] += bs[(yi0 - yj0 + 11) * 23 + (xi0 - xj0 + 11)] + mk0.x;
            s[tj][1] += bs[(yi0 - yj1 + 11) * 23 + (xi0 - xj1 + 11)] + mk0.y;
            s[tj][2] += bs[(yi1 - yj0 + 11) * 23 + (xi1 - xj0 + 11)] + mk1.x;
            s[tj][3] += bs[(yi1 - yj1 + 11) * 23 + (xi1 - xj1 + 11)] + mk1.y;
            mx0 = fmaxf(mx0, fmaxf(s[tj][0], s[tj][1]));
            mx1 = fmaxf(mx1, fmaxf(s[tj][2], s[tj][3]));
        }
        mx0 = fmaxf(mx0, __shfl_xor_sync(0xffffffffu, mx0, 1));
        mx0 = fmaxf(mx0, __shfl_xor_sync(0xffffffffu, mx0, 2));
        mx1 = fmaxf(mx1, __shfl_xor_sync(0xffffffffu, mx1, 1));
        mx1 = fmaxf(mx1, __shfl_xor_sync(0xffffffffu, mx1, 2));

        float sum0 = 0.0f, sum1 = 0.0f;
#pragma unroll
        for (int tj = 0; tj < 18; tj++) {
            s[tj][0] = __expf(s[tj][0] - mx0);
            s[tj][1] = __expf(s[tj][1] - mx0);
            s[tj][2] = __expf(s[tj][2] - mx1);
            s[tj][3] = __expf(s[tj][3] - mx1);
            sum0 += s[tj][0] + s[tj][1];
            sum1 += s[tj][2] + s[tj][3];
        }
        sum0 += __shfl_xor_sync(0xffffffffu, sum0, 1);
        sum0 += __shfl_xor_sync(0xffffffffu, sum0, 2);
        sum1 += __shfl_xor_sync(0xffffffffu, sum1, 1);
        sum1 += __shfl_xor_sync(0xffffffffu, sum1, 2);
        float inv0 = 1.0f / sum0;
        float inv1 = 1.0f / sum1;

        float o[4][4];
#pragma unroll
        for (int nd = 0; nd < 4; nd++)
#pragma unroll
            for (int r = 0; r < 4; r++) o[nd][r] = 0.0f;

#pragma unroll
        for (int t = 0; t < 9; t++) {
            uint32_t ph[4], pl[4];
#pragma unroll
            for (int rg = 0; rg < 4; rg++) {
                float a = s[t * 2 + (rg >> 1)][(rg & 1) * 2 + 0];
                float c = s[t * 2 + (rg >> 1)][(rg & 1) * 2 + 1];
                __nv_bfloat16 ha, la, hc, lc;
                split1(a, ha, la);
                split1(c, hc, lc);
                ph[rg] = pkbf(ha, hc);
                pl[rg] = pkbf(la, lc);
            }
            uint32_t vbh[2][4], vbl[2][4];
#pragma unroll
            for (int u = 0; u < 2; u++) {
                LDM4(vbh[u], vh_b + u * 4608 + t * 512);
                LDM4(vbl[u], vl_b + u * 4608 + t * 512);
            }
#pragma unroll
            for (int nd = 0; nd < 4; nd++) {
                int u = nd >> 1, rr = (nd & 1) * 2;
                MMA16816(o[nd], ph, vbh[u][rr], vbh[u][rr + 1]);
                MMA16816(o[nd], pl, vbh[u][rr], vbh[u][rr + 1]);
                MMA16816(o[nd], ph, vbl[u][rr], vbl[u][rr + 1]);
            }
        }

        size_t ob = ((size_t)b * NTOK) * DIM + h * HD;
#pragma unroll
        for (int nd = 0; nd < 4; nd++) {
            int d = nd * 8 + (lane & 3) * 2;
            float a0 = o[nd][0] * inv0, a1 = o[nd][1] * inv0;
            float a2 = o[nd][2] * inv1, a3 = o[nd][3] * inv1;
            size_t i0 = ob + (size_t)r0 * DIM + d;
            size_t i1 = ob + (size_t)r1 * DIM + d;
            *(ushort2*)&g_oh[i0] = make_ushort2(
                __half_as_ushort(__float2half_rn(a0)),
                __half_as_ushort(__float2half_rn(a1)));
            *(ushort2*)&g_oh[i1] = make_ushort2(
                __half_as_ushort(__float2half_rn(a2)),
                __half_as_ushort(__float2half_rn(a3)));
        }
    }
}

// ---------------------------------------------------------------------------
// launch — size-based input resolution (order-robust)
// ---------------------------------------------------------------------------
extern "C" void kernel_launch(void* const* d_in, const int* in_sizes, int n_in,
                              void* d_out, int out_size)
{
    int ix = 0, imask = 1, iwqkv = 2, ils = 5, iw1 = 6, iw2 = 8, iwproj = 9;
    int small[4] = {3, 4, 7, 10};
    int ns = 0;
    int sm_tmp[8];
    int fx = -1, fmask = -1, fwqkv = -1, fls = -1, fw1 = -1, fw2 = -1, fwp = -1;
    for (int i = 0; i < n_in; i++) {
        switch (in_sizes[i]) {
            case 37748736: fx = i; break;
            case 1327104:  fmask = i; break;
            case 786432:   fwqkv = i; break;
            case 16:       fls = i; break;
            case 1024:     fw1 = i; break;
            case 8192:     fw2 = i; break;
            case 262144:   fwp = i; break;
            case 512:      if (ns < 8) sm_tmp[ns++] = i; break;
            default: break;
        }
    }
    if (fx >= 0 && fmask >= 0 && fwqkv >= 0 && fls >= 0 && fw1 >= 0 &&
        fw2 >= 0 && fwp >= 0 && ns >= 4) {
        ix = fx; imask = fmask; iwqkv = fwqkv; ils = fls;
        iw1 = fw1; iw2 = fw2; iwproj = fwp;
        for (int t = 0; t < 4; t++) small[t] = sm_tmp[t];
    }

    const float* x           = (const float*)d_in[ix];
    const float* mask        = (const float*)d_in[imask];
    const float* w_qkv       = (const float*)d_in[iwqkv];
    const float* q_bias      = (const float*)d_in[small[0]];
    const float* v_bias      = (const float*)d_in[small[1]];
    const float* logit_scale = (const float*)d_in[ils];
    const float* w1          = (const float*)d_in[iw1];
    const float* b1          = (const float*)d_in[small[2]];
    const float* w2          = (const float*)d_in[iw2];
    const float* w_proj      = (const float*)d_in[iwproj];
    const float* b_proj      = (const float*)d_in[small[3]];
    float* out = (float*)d_out;
    (void)out_size;

    cudaFuncSetAttribute(attn_kernel,
                         cudaFuncAttributeMaxDynamicSharedMemorySize, ATT_SMEM);

    // 0) fused operand prep: x -> fp16; weights -> fp16 hi/lo (one launch)
    split_all_kernel<<<SPL_BLOCKS, 256>>>(x, w_qkv, w_proj);

    // 1) CPB bias table
    cpb_kernel<<<529, 128>>>(w1, b1, w2);

    // 2) QKV: (73728 x 512) @ (1536 x 512)^T — fp16 2-term, BK=16 (R13)
    {
        dim3 grid(1536 / 128, (BW * NTOK) / 128);
        gemm_b<0><<<grid, 256>>>(q_bias, v_bias, nullptr);
    }

    // 3) attention per (b,h) — bf16 3-pass MMA, 4 warps (R13)
    attn_kernel<<<BW * NH, 128, ATT_SMEM>>>(mask, logit_scale);

    // 4) proj: (73728 x 512) @ (512 x 512)^T — fp16 2-term, BK=16 (R13)
    {
        dim3 grid(DIM / 128, (BW * NTOK) / 128);
        gemm_b<1><<<grid, 256>>>(b_proj, nullptr, out);
    }
}